// round 12
// baseline (speedup 1.0000x reference)
#include <cuda_runtime.h>
#include <cuda_bf16.h>
#include <float.h>
#include <math.h>

// Problem constants (from reference)
#define H 512
#define W 512
#define PSIZE 4
#define NEUR 32
#define TOPK 4
#define S2 16
#define NH 509            // (512 - 3) / 1
#define NW 509
#define NZ (NH * NW)      // 259081
#define EPSV 1e-8f
// near-tie window: >> fast-vs-exact pre delta (~1e-6), << typical 4th/5th
// gap (~6e-3) -> exact path runs on a few % of rows
#define TIE_TAU 5e-4f

#define WARPS_PER_BLOCK 8

// One warp per patch z; lane n = neuron n.
//
// R10 memory fix: the old per-lane row load (64B lane stride) made every
// LDG.128 touch 16 cache lines at 32B each -> 64 sector-wavefronts per
// warp through L1tex (measured L1=77%, the binding pipe). Now the warp
// loads its 2048B Wz chunk lane-CONTIGUOUS (4x LDG.128, 4 full 128B lines
// each = 16 wavefronts) and transposes neuron-major through a per-warp
// 2KB smem tile. Swizzle slot(n,q) = n*4 + ((q + (n>>1)) & 3) makes both
// the STS.128 scatter and LDS.128 row-gather bank-conflict-free per 8-lane
// phase. Values reaching w[] are bit-identical to R9.
//
// Numerics (unchanged): fast FMA path + REDUX top-4; exact XLA-emulation
// rescue (rounded mul->add, no FMA, divide-first) on warps whose 4th/5th
// gap is < TIE_TAU. pre >= 0 always, so float order == unsigned-bit order.
__device__ __forceinline__ float top4_threshold(unsigned mybits, int lane)
{
    const unsigned FULL = 0xFFFFFFFFu;
    unsigned active = mybits;
    unsigned thrbits = 0;
#pragma unroll
    for (int k = 0; k < TOPK; k++) {
        thrbits = __reduce_max_sync(FULL, active);
        unsigned ball = __ballot_sync(FULL, active == thrbits);
        if (lane == (int)__ffs(ball) - 1) active = 0u;
    }
    return __uint_as_float(thrbits);
}

__global__ __launch_bounds__(256, 6)
void topk_layer2d_kernel(const float* __restrict__ x,
                         const float* __restrict__ Wz,
                         float* __restrict__ out)
{
    __shared__ float4 sw[WARPS_PER_BLOCK][NEUR * 4];   // 2KB per warp

    const int lane = threadIdx.x & 31;
    const int warp = threadIdx.x >> 5;
    const int z    = blockIdx.x * WARPS_PER_BLOCK + warp;
    if (z >= NZ) return;

    const int r = z / NW;
    const int c = z - r * NW;

    // ---- Wz chunk: 4 lane-contiguous float4 loads (full-line wavefronts) ----
    const float4* src = reinterpret_cast<const float4*>(Wz) + (size_t)z * (NEUR * 4);
    float4 g0 = src[lane];
    float4 g1 = src[32 + lane];
    float4 g2 = src[64 + lane];
    float4 g3 = src[96 + lane];

    // ---- scatter into swizzled smem tile (conflict-free STS.128) ----
    {
        int j, n, q;
        j = lane;        n = j >> 2; q = j & 3; sw[warp][n*4 + ((q + (n>>1)) & 3)] = g0;
        j = 32 + lane;   n = j >> 2; q = j & 3; sw[warp][n*4 + ((q + (n>>1)) & 3)] = g1;
        j = 64 + lane;   n = j >> 2; q = j & 3; sw[warp][n*4 + ((q + (n>>1)) & 3)] = g2;
        j = 96 + lane;   n = j >> 2; q = j & 3; sw[warp][n*4 + ((q + (n>>1)) & 3)] = g3;
    }
    __syncwarp();

    // ---- gather own neuron row (conflict-free LDS.128) ----
    float w[S2];
    {
        const int rot = (lane >> 1) & 3;
#pragma unroll
        for (int q = 0; q < 4; q++) {
            float4 v = sw[warp][lane*4 + ((q + rot) & 3)];
            w[q*4 + 0] = v.x; w[q*4 + 1] = v.y; w[q*4 + 2] = v.z; w[q*4 + 3] = v.w;
        }
    }

    // ---- patch (uniform-address broadcast loads, L1-resident) ----
    float p[S2];
#pragma unroll
    for (int a = 0; a < PSIZE; a++)
#pragma unroll
        for (int b = 0; b < PSIZE; b++)
            p[a * PSIZE + b] = __ldg(&x[(r + a) * W + (c + b)]);

    const unsigned FULL = 0xFFFFFFFFu;

    // ================= FAST PATH =================
    float pacc = 0.f, wacc = 0.f, dp = 0.f;
#pragma unroll
    for (int d = 0; d < S2; d++) {
        pacc = fmaf(p[d], p[d], pacc);
        wacc = fmaf(w[d], w[d], wacc);
        dp   = fmaf(w[d], p[d], dp);
    }
    const float den = (sqrtf(wacc) + EPSV) * (sqrtf(pacc) + EPSV);
    float pre = __fdividef(dp, den);

    float thr = top4_threshold(__float_as_uint(pre), lane);

    // ================= EXACT RESCUE (rare, warp-uniform) =================
    // Risky iff MORE than 4 lanes are candidates at thr - tau (4th/5th gap
    // below tau). Exactly 4 candidates -> gap > tau -> fast ordering safe.
    const unsigned nearMask = __ballot_sync(FULL, pre >= thr - TIE_TAU);
    if (__popc(nearMask) > 4) {
        // patch norm: rounded square + sequential rounded adds, ascending
        float pa = 0.f;
#pragma unroll
        for (int d = 0; d < S2; d++)
            pa = __fadd_rn(pa, __fmul_rn(p[d], p[d]));
        const float pden = __fadd_rn(__fsqrt_rn(pa), EPSV);
        // pn is warp-uniform: lane d (<16) does element d's rounded divide
        const float pn_mine = (lane < S2) ? __fdiv_rn(p[lane], pden) : 0.f;

        float wa = 0.f;
#pragma unroll
        for (int d = 0; d < S2; d++)
            wa = __fadd_rn(wa, __fmul_rn(w[d], w[d]));
        const float wden = __fadd_rn(__fsqrt_rn(wa), EPSV);

        // pre = reduce(mul): rounded mul, rounded add, ascending (no FMA)
        float acc = 0.f;
#pragma unroll
        for (int d = 0; d < S2; d++) {
            const float pn_d = __shfl_sync(FULL, pn_mine, d);
            const float wn_d = __fdiv_rn(w[d], wden);
            acc = __fadd_rn(acc, __fmul_rn(wn_d, pn_d));
        }
        pre = acc;   // exact values for this row (matches R6 bit-for-bit)
        thr = top4_threshold(__float_as_uint(pre), lane);
    }

    // coalesced 128B store per warp
    out[(size_t)z * NEUR + lane] = (pre >= thr) ? pre : 0.f;
}

extern "C" void kernel_launch(void* const* d_in, const int* in_sizes, int n_in,
                              void* d_out, int out_size)
{
    const float* x  = (const float*)d_in[0];   // (512, 512) fp32
    const float* Wz = (const float*)d_in[1];   // (NZ, 32, 16) fp32
    float* out = (float*)d_out;                // (NZ, 32) fp32

    const int blocks = (NZ + WARPS_PER_BLOCK - 1) / WARPS_PER_BLOCK;
    topk_layer2d_kernel<<<blocks, WARPS_PER_BLOCK * 32>>>(x, Wz, out);
}

// round 14
// speedup vs baseline: 1.1752x; 1.1752x over previous
#include <cuda_runtime.h>
#include <cuda_bf16.h>
#include <float.h>
#include <math.h>

// Problem constants (from reference)
#define H 512
#define W 512
#define PSIZE 4
#define NEUR 32
#define TOPK 4
#define S2 16
#define NH 509            // (512 - 3) / 1
#define NW 509
#define NZ (NH * NW)      // 259081
#define EPSV 1e-8f
// near-tie window: >> fast-vs-exact pre delta (~1e-6), << typical 4th/5th
// gap (~6e-3) -> exact path runs on a few % of rows
#define TIE_TAU 5e-4f

#define WARPS_PER_BLOCK 8
#define Z_PER_WARP 2

// R13: the kernel has been stuck at ~3.9 TB/s (48% DRAM) across three very
// different instruction mixes -> Little's-law limited: only 2KB of Wz in
// flight per warp. Now each warp owns TWO adjacent z and front-batches all
// 8 lane-contiguous LDG.128 (4KB in flight, 2x MLP) before consuming
// anything. Per-z processing (swizzled smem transpose, fast FMA path,
// REDUX top-4, exact XLA-emulation rescue) is unchanged -> bit-identical
// output to R12.
__device__ __forceinline__ float top4_threshold(unsigned mybits, int lane)
{
    const unsigned FULL = 0xFFFFFFFFu;
    unsigned active = mybits;   // pre >= 0 always -> float order == uint order
    unsigned thrbits = 0;
#pragma unroll
    for (int k = 0; k < TOPK; k++) {
        thrbits = __reduce_max_sync(FULL, active);
        unsigned ball = __ballot_sync(FULL, active == thrbits);
        if (lane == (int)__ffs(ball) - 1) active = 0u;
    }
    return __uint_as_float(thrbits);
}

__global__ __launch_bounds__(256, 5)
void topk_layer2d_kernel(const float* __restrict__ x,
                         const float* __restrict__ Wz,
                         float* __restrict__ out)
{
    __shared__ float4 sw[WARPS_PER_BLOCK][Z_PER_WARP][NEUR * 4]; // 4KB/warp

    const int lane = threadIdx.x & 31;
    const int warp = threadIdx.x >> 5;
    const int gw   = blockIdx.x * WARPS_PER_BLOCK + warp;
    const int z0   = gw * Z_PER_WARP;
    if (z0 >= NZ) return;
    const bool has_z1 = (z0 + 1) < NZ;

    // ---- front-batch ALL Wz loads: 8 lane-contiguous LDG.128 (4KB/warp in
    //      flight; full-line wavefronts) ----
    const float4* src = reinterpret_cast<const float4*>(Wz) + (size_t)z0 * (NEUR * 4);
    float4 g[2 * 4];
#pragma unroll
    for (int i = 0; i < 4; i++)
        g[i] = src[i * 32 + lane];
    if (has_z1) {   // warp-uniform
#pragma unroll
        for (int i = 0; i < 4; i++)
            g[4 + i] = src[128 + i * 32 + lane];
    }

    // ---- scatter both tiles into swizzled smem (conflict-free STS.128) ----
#pragma unroll
    for (int t = 0; t < Z_PER_WARP; t++) {
        if (t == 1 && !has_z1) break;
#pragma unroll
        for (int i = 0; i < 4; i++) {
            const int j = i * 32 + lane;
            const int n = j >> 2, q = j & 3;
            sw[warp][t][n * 4 + ((q + (n >> 1)) & 3)] = g[t * 4 + i];
        }
    }
    __syncwarp();

    const unsigned FULL = 0xFFFFFFFFu;

#pragma unroll
    for (int t = 0; t < Z_PER_WARP; t++) {
        const int z = z0 + t;
        if (t == 1 && !has_z1) break;   // warp-uniform

        const int r = z / NW;
        const int c = z - r * NW;

        // ---- gather own neuron row (conflict-free LDS.128) ----
        float w[S2];
        {
            const int rot = (lane >> 1) & 3;
#pragma unroll
            for (int q = 0; q < 4; q++) {
                float4 v = sw[warp][t][lane * 4 + ((q + rot) & 3)];
                w[q*4+0] = v.x; w[q*4+1] = v.y; w[q*4+2] = v.z; w[q*4+3] = v.w;
            }
        }

        // ---- patch (uniform-address broadcast loads, L1-resident) ----
        float p[S2];
#pragma unroll
        for (int a = 0; a < PSIZE; a++)
#pragma unroll
            for (int b = 0; b < PSIZE; b++)
                p[a * PSIZE + b] = __ldg(&x[(r + a) * W + (c + b)]);

        // ================= FAST PATH =================
        float pacc = 0.f, wacc = 0.f, dp = 0.f;
#pragma unroll
        for (int d = 0; d < S2; d++) {
            pacc = fmaf(p[d], p[d], pacc);
            wacc = fmaf(w[d], w[d], wacc);
            dp   = fmaf(w[d], p[d], dp);
        }
        const float den = (sqrtf(wacc) + EPSV) * (sqrtf(pacc) + EPSV);
        float pre = __fdividef(dp, den);

        float thr = top4_threshold(__float_as_uint(pre), lane);

        // ============ EXACT RESCUE (rare, warp-uniform) ============
        // Risky iff MORE than 4 lanes are candidates at thr - tau (the
        // 4th/5th gap is below tau). Exactly 4 -> gap > tau -> safe.
        const unsigned nearMask = __ballot_sync(FULL, pre >= thr - TIE_TAU);
        if (__popc(nearMask) > 4) {
            // patch norm: rounded square + sequential rounded adds, ascending
            float pa = 0.f;
#pragma unroll
            for (int d = 0; d < S2; d++)
                pa = __fadd_rn(pa, __fmul_rn(p[d], p[d]));
            const float pden = __fadd_rn(__fsqrt_rn(pa), EPSV);
            // pn is warp-uniform: lane d (<16) does element d's rounded divide
            const float pn_mine = (lane < S2) ? __fdiv_rn(p[lane], pden) : 0.f;

            float wa = 0.f;
#pragma unroll
            for (int d = 0; d < S2; d++)
                wa = __fadd_rn(wa, __fmul_rn(w[d], w[d]));
            const float wden = __fadd_rn(__fsqrt_rn(wa), EPSV);

            // pre = reduce(mul): rounded mul, rounded add, ascending (no FMA)
            float acc = 0.f;
#pragma unroll
            for (int d = 0; d < S2; d++) {
                const float pn_d = __shfl_sync(FULL, pn_mine, d);
                const float wn_d = __fdiv_rn(w[d], wden);
                acc = __fadd_rn(acc, __fmul_rn(wn_d, pn_d));
            }
            pre = acc;   // exact values for this row (matches R6 bit-for-bit)
            thr = top4_threshold(__float_as_uint(pre), lane);
        }

        // coalesced 128B store per warp
        out[(size_t)z * NEUR + lane] = (pre >= thr) ? pre : 0.f;
    }
}

extern "C" void kernel_launch(void* const* d_in, const int* in_sizes, int n_in,
                              void* d_out, int out_size)
{
    const float* x  = (const float*)d_in[0];   // (512, 512) fp32
    const float* Wz = (const float*)d_in[1];   // (NZ, 32, 16) fp32
    float* out = (float*)d_out;                // (NZ, 32) fp32

    const int z_per_block = WARPS_PER_BLOCK * Z_PER_WARP;
    const int blocks = (NZ + z_per_block - 1) / z_per_block;
    topk_layer2d_kernel<<<blocks, WARPS_PER_BLOCK * 32>>>(x, Wz, out);
}

// round 16
// speedup vs baseline: 1.1798x; 1.0039x over previous
#include <cuda_runtime.h>
#include <cuda_bf16.h>
#include <float.h>
#include <math.h>
#include <stdint.h>

// Problem constants (from reference)
#define H 512
#define W 512
#define PSIZE 4
#define NEUR 32
#define TOPK 4
#define S2 16
#define NH 509            // (512 - 3) / 1
#define NW 509
#define NZ (NH * NW)      // 259081
#define EPSV 1e-8f
// near-tie window: >> fast-vs-exact pre delta (~1e-6), << typical 4th/5th
// gap (~6e-3) -> exact path runs on a few % of rows
#define TIE_TAU 5e-4f

#define WARPS_PER_BLOCK 8
#define CHUNK 8            // z per warp, double-buffered cp.async pipeline

// R16 (= R15 + missing stdint include): R13 proved Little's-law limiting
// (front-batch 2x MLP -> 48->57% DRAM). A one-shot register burst keeps
// bytes in flight only ~40% of warp life. Each warp now streams CHUNK z
// through a 2-buffer cp.async.cg pipeline: tile t+1 is in flight WHILE
// tile t is computed -> steady-state in-flight at ~90% duty, no register
// staging (occupancy up), Wz bypasses L1 (.cg -> L2 only; x patches keep
// the cache). Transpose slots, fast path, REDUX top-4 and the exact
// XLA-emulation rescue are unchanged -> bit-identical output.
__device__ __forceinline__ void cp16(unsigned int dst_smem, const void* src) {
    asm volatile("cp.async.cg.shared.global [%0], [%1], 16;"
                 :: "r"(dst_smem), "l"(src));
}

__device__ __forceinline__ float top4_threshold(unsigned mybits, int lane)
{
    const unsigned FULL = 0xFFFFFFFFu;
    unsigned active = mybits;   // pre >= 0 always -> float order == uint order
    unsigned thrbits = 0;
#pragma unroll
    for (int k = 0; k < TOPK; k++) {
        thrbits = __reduce_max_sync(FULL, active);
        unsigned ball = __ballot_sync(FULL, active == thrbits);
        if (lane == (int)__ffs(ball) - 1) active = 0u;
    }
    return __uint_as_float(thrbits);
}

__global__ __launch_bounds__(256)
void topk_layer2d_kernel(const float* __restrict__ x,
                         const float* __restrict__ Wz,
                         float* __restrict__ out)
{
    // 2 buffers x 2KB per warp = 32KB per block
    __shared__ float4 sw[WARPS_PER_BLOCK][2][NEUR * 4];

    const int lane = threadIdx.x & 31;
    const int warp = threadIdx.x >> 5;
    const int gw   = blockIdx.x * WARPS_PER_BLOCK + warp;
    const int z0   = gw * CHUNK;
    if (z0 >= NZ) return;
    const int nzw = min(CHUNK, NZ - z0);   // warp-uniform

    // precomputed swizzled smem byte-addresses for this lane's 4 slots
    // slot(j): n=j>>2, q=j&3 -> n*4 + ((q + (n>>1)) & 3)
    unsigned int dst_addr[2][4];
#pragma unroll
    for (int buf = 0; buf < 2; buf++) {
        unsigned int base =
            (unsigned int)__cvta_generic_to_shared(&sw[warp][buf][0]);
#pragma unroll
        for (int i = 0; i < 4; i++) {
            const int j = i * 32 + lane;
            const int n = j >> 2, q = j & 3;
            dst_addr[buf][i] =
                base + (unsigned int)(n * 4 + ((q + (n >> 1)) & 3)) * 16u;
        }
    }

    const float4* wbase =
        reinterpret_cast<const float4*>(Wz) + (size_t)z0 * (NEUR * 4);

    // ---- prologue: stream tile 0 into buf 0 ----
#pragma unroll
    for (int i = 0; i < 4; i++)
        cp16(dst_addr[0][i], wbase + (i * 32 + lane));
    asm volatile("cp.async.commit_group;" ::: "memory");

    const unsigned FULL = 0xFFFFFFFFu;

    for (int t = 0; t < nzw; t++) {          // warp-uniform trip count
        const int z   = z0 + t;
        const int buf = t & 1;

        // ---- prefetch next tile into the other buffer ----
        if (t + 1 < nzw) {
            const float4* nsrc = wbase + (size_t)(t + 1) * (NEUR * 4);
#pragma unroll
            for (int i = 0; i < 4; i++)
                cp16(dst_addr[(t + 1) & 1][i], nsrc + (i * 32 + lane));
        }
        asm volatile("cp.async.commit_group;" ::: "memory");
        // <=1 group outstanding -> tile t's group is complete
        asm volatile("cp.async.wait_group 1;" ::: "memory");
        __syncwarp();

        // ---- gather own neuron row (conflict-free LDS.128) ----
        float w[S2];
        {
            const int rot = (lane >> 1) & 3;
#pragma unroll
            for (int q = 0; q < 4; q++) {
                float4 v = sw[warp][buf][lane * 4 + ((q + rot) & 3)];
                w[q*4+0] = v.x; w[q*4+1] = v.y; w[q*4+2] = v.z; w[q*4+3] = v.w;
            }
        }
        __syncwarp();   // all lanes done reading before this buffer refills

        const int r = z / NW;
        const int c = z - r * NW;

        // ---- patch (uniform-address broadcast loads, L1-resident) ----
        float p[S2];
#pragma unroll
        for (int a = 0; a < PSIZE; a++)
#pragma unroll
            for (int b = 0; b < PSIZE; b++)
                p[a * PSIZE + b] = __ldg(&x[(r + a) * W + (c + b)]);

        // ================= FAST PATH =================
        float pacc = 0.f, wacc = 0.f, dp = 0.f;
#pragma unroll
        for (int d = 0; d < S2; d++) {
            pacc = fmaf(p[d], p[d], pacc);
            wacc = fmaf(w[d], w[d], wacc);
            dp   = fmaf(w[d], p[d], dp);
        }
        const float den = (sqrtf(wacc) + EPSV) * (sqrtf(pacc) + EPSV);
        float pre = __fdividef(dp, den);

        float thr = top4_threshold(__float_as_uint(pre), lane);

        // ============ EXACT RESCUE (rare, warp-uniform) ============
        // Risky iff MORE than 4 lanes are candidates at thr - tau (the
        // 4th/5th gap is below tau). Exactly 4 -> gap > tau -> safe.
        const unsigned nearMask = __ballot_sync(FULL, pre >= thr - TIE_TAU);
        if (__popc(nearMask) > 4) {
            // patch norm: rounded square + sequential rounded adds, ascending
            float pa = 0.f;
#pragma unroll
            for (int d = 0; d < S2; d++)
                pa = __fadd_rn(pa, __fmul_rn(p[d], p[d]));
            const float pden = __fadd_rn(__fsqrt_rn(pa), EPSV);
            // pn is warp-uniform: lane d (<16) does element d's rounded divide
            const float pn_mine = (lane < S2) ? __fdiv_rn(p[lane], pden) : 0.f;

            float wa = 0.f;
#pragma unroll
            for (int d = 0; d < S2; d++)
                wa = __fadd_rn(wa, __fmul_rn(w[d], w[d]));
            const float wden = __fadd_rn(__fsqrt_rn(wa), EPSV);

            // pre = reduce(mul): rounded mul, rounded add, ascending (no FMA)
            float acc = 0.f;
#pragma unroll
            for (int d = 0; d < S2; d++) {
                const float pn_d = __shfl_sync(FULL, pn_mine, d);
                const float wn_d = __fdiv_rn(w[d], wden);
                acc = __fadd_rn(acc, __fmul_rn(wn_d, pn_d));
            }
            pre = acc;   // exact values for this row (matches R6 bit-for-bit)
            thr = top4_threshold(__float_as_uint(pre), lane);
        }

        // coalesced 128B store per warp
        out[(size_t)z * NEUR + lane] = (pre >= thr) ? pre : 0.f;
    }
}

extern "C" void kernel_launch(void* const* d_in, const int* in_sizes, int n_in,
                              void* d_out, int out_size)
{
    const float* x  = (const float*)d_in[0];   // (512, 512) fp32
    const float* Wz = (const float*)d_in[1];   // (NZ, 32, 16) fp32
    float* out = (float*)d_out;                // (NZ, 32) fp32

    const int z_per_block = WARPS_PER_BLOCK * CHUNK;
    const int blocks = (NZ + z_per_block - 1) / z_per_block;
    topk_layer2d_kernel<<<blocks, WARPS_PER_BLOCK * 32>>>(x, Wz, out);
}